// round 2
// baseline (speedup 1.0000x reference)
#include <cuda_runtime.h>
#include <math.h>

#define SQ 2048
#define DM 1024
#define NH 16
#define HD 64

// Scratch (allocation-free: device globals)
static __device__ float g_q[NH * SQ * HD];
static __device__ float g_k[NH * SQ * HD];
static __device__ float g_v[NH * SQ * HD];
static __device__ float g_wv[SQ * DM];

// ---------------------------------------------------------------------------
// GEMM: C = A[M,K] * W[N,K]^T + bias   (both A and W are K-contiguous => NT)
// MODE 0: C row-major [M,N]
// MODE 1: C in head layout: n -> (h = n/64, d = n%64), C[(h*SQ + m)*64 + d]
// BM=BN=64, BK=16, 256 threads, 4x4 per thread.
// ---------------------------------------------------------------------------
template <int MODE>
__global__ void __launch_bounds__(256) gemm_nt(
    const float* __restrict__ A, const float* __restrict__ W,
    const float* __restrict__ bias, float* __restrict__ C,
    int M, int N, int K)
{
    __shared__ float As[64][17];
    __shared__ float Ws[64][17];

    const int tx = threadIdx.x & 15;
    const int ty = threadIdx.x >> 4;
    const int m0 = blockIdx.y * 64;
    const int n0 = blockIdx.x * 64;

    float acc[4][4];
#pragma unroll
    for (int i = 0; i < 4; i++)
#pragma unroll
        for (int j = 0; j < 4; j++) acc[i][j] = 0.f;

    const int lr = threadIdx.x >> 2;          // 0..63
    const int lc = (threadIdx.x & 3) << 2;    // 0,4,8,12

    for (int k0 = 0; k0 < K; k0 += 16) {
        float4 av = *reinterpret_cast<const float4*>(A + (size_t)(m0 + lr) * K + k0 + lc);
        float4 wv = *reinterpret_cast<const float4*>(W + (size_t)(n0 + lr) * K + k0 + lc);
        As[lr][lc + 0] = av.x; As[lr][lc + 1] = av.y; As[lr][lc + 2] = av.z; As[lr][lc + 3] = av.w;
        Ws[lr][lc + 0] = wv.x; Ws[lr][lc + 1] = wv.y; Ws[lr][lc + 2] = wv.z; Ws[lr][lc + 3] = wv.w;
        __syncthreads();
#pragma unroll
        for (int kk = 0; kk < 16; kk++) {
            float a[4], w[4];
#pragma unroll
            for (int i = 0; i < 4; i++) a[i] = As[ty * 4 + i][kk];
#pragma unroll
            for (int j = 0; j < 4; j++) w[j] = Ws[tx * 4 + j][kk];
#pragma unroll
            for (int i = 0; i < 4; i++)
#pragma unroll
                for (int j = 0; j < 4; j++) acc[i][j] = fmaf(a[i], w[j], acc[i][j]);
        }
        __syncthreads();
    }

#pragma unroll
    for (int i = 0; i < 4; i++) {
        const int m = m0 + ty * 4 + i;
#pragma unroll
        for (int j = 0; j < 4; j++) {
            const int n = n0 + tx * 4 + j;
            float v = acc[i][j] + (bias ? bias[n] : 0.f);
            if (MODE == 0) {
                C[(size_t)m * N + n] = v;
            } else {
                const int h = n >> 6;
                const int d = n & 63;
                C[((size_t)h * SQ + m) * HD + d] = v;
            }
        }
    }
}

// ---------------------------------------------------------------------------
// RoPE (interleaved pairs) + fold in scale = hd^-0.25 for both q and k.
// grid = 2 * NH * SQ blocks of 32 threads; thread j handles pair (2j, 2j+1).
// fp64 trig for accuracy (cheap: 4M evals).
// ---------------------------------------------------------------------------
__global__ void rope_kernel(const float* __restrict__ inv_freq)
{
    const int j = threadIdx.x;               // 0..31
    const int idx = blockIdx.x;              // 0 .. 2*NH*SQ-1
    const int s = idx & (SQ - 1);
    const int hh = (idx >> 11) & (NH - 1);
    const int arr = idx >> 15;

    float* base = (arr ? g_k : g_q) + ((size_t)hh * SQ + s) * HD;
    const double f = (double)s * (double)inv_freq[j];
    const float c = (float)cos(f);
    const float sn = (float)sin(f);
    const float a = base[2 * j];
    const float b = base[2 * j + 1];
    const float scale = 0.3535533905932738f;  // 64^(-1/4)
    base[2 * j]     = scale * (a * c - b * sn);
    base[2 * j + 1] = scale * (a * sn + b * c);
}

// ---------------------------------------------------------------------------
// Attention: per (64 query rows, head) block. Flash-style online softmax,
// also writes the pre-softmax (post-zscale/mask) qk tile to gmem.
// smem: Qs[64][65], Ks[64][65] (reused for P), Vs[64][65], zc[64]
// 256 threads, 4x4 micro-tiles. Row stats (m,l) are register-resident,
// replicated within each 16-lane tx-group via shuffles.
// ---------------------------------------------------------------------------
__global__ void __launch_bounds__(256) attn_kernel(
    const float* __restrict__ mask, const float* __restrict__ Zf,
    float* __restrict__ qk_out)
{
    extern __shared__ float sm[];
    float* Qs = sm;                       // 64*65
    float* Ks = sm + 64 * 65;             // K tile, reused as P
    float* Vs = sm + 2 * 64 * 65;         // V tile
    float* zc = sm + 3 * 64 * 65;         // 64 per-key zscale

    const int tid = threadIdx.x;
    const int tx = tid & 15;
    const int ty = tid >> 4;
    const int q0 = blockIdx.x * 64;
    const int h = blockIdx.y;

    const float zfac = fminf(fmaxf(log1pf(expf(Zf[0])), 1e-5f), 1e-4f);

    const float* qg = g_q + ((size_t)h * SQ + q0) * HD;
    const float* kg = g_k + (size_t)h * SQ * HD;
    const float* vg = g_v + (size_t)h * SQ * HD;

    // Load Q tile (visible after first __syncthreads in the loop)
#pragma unroll
    for (int t = 0; t < 4; t++) {
        const int lin = tid + t * 256;
        const int r = lin >> 4;
        const int c = (lin & 15) << 2;
        float4 v4 = *reinterpret_cast<const float4*>(qg + r * HD + c);
        Qs[r * 65 + c + 0] = v4.x; Qs[r * 65 + c + 1] = v4.y;
        Qs[r * 65 + c + 2] = v4.z; Qs[r * 65 + c + 3] = v4.w;
    }

    float acc[4][4];
    float m_i[4], l_i[4];
#pragma unroll
    for (int i = 0; i < 4; i++) {
        m_i[i] = -INFINITY;
        l_i[i] = 0.f;
#pragma unroll
        for (int j = 0; j < 4; j++) acc[i][j] = 0.f;
    }

    for (int kt = 0; kt < SQ / 64; kt++) {
        __syncthreads();  // previous tile's P/V reads done (and Q load on iter 0)

        const float* kgt = kg + (size_t)kt * 64 * HD;
        const float* vgt = vg + (size_t)kt * 64 * HD;
#pragma unroll
        for (int t = 0; t < 4; t++) {
            const int lin = tid + t * 256;
            const int r = lin >> 4;
            const int c = (lin & 15) << 2;
            float4 k4 = *reinterpret_cast<const float4*>(kgt + r * HD + c);
            float4 v4 = *reinterpret_cast<const float4*>(vgt + r * HD + c);
            Ks[r * 65 + c + 0] = k4.x; Ks[r * 65 + c + 1] = k4.y;
            Ks[r * 65 + c + 2] = k4.z; Ks[r * 65 + c + 3] = k4.w;
            Vs[r * 65 + c + 0] = v4.x; Vs[r * 65 + c + 1] = v4.y;
            Vs[r * 65 + c + 2] = v4.z; Vs[r * 65 + c + 3] = v4.w;
        }
        __syncthreads();

        if (tid < 64) zc[tid] = (Ks[tid * 65] == 0.f) ? zfac : 1.f;

        // S = Q * K^T for this tile
        float sacc[4][4];
#pragma unroll
        for (int i = 0; i < 4; i++)
#pragma unroll
            for (int j = 0; j < 4; j++) sacc[i][j] = 0.f;

#pragma unroll 4
        for (int kk = 0; kk < HD; kk++) {
            float a[4], b[4];
#pragma unroll
            for (int i = 0; i < 4; i++) a[i] = Qs[(ty * 4 + i) * 65 + kk];
#pragma unroll
            for (int j = 0; j < 4; j++) b[j] = Ks[(tx * 4 + j) * 65 + kk];
#pragma unroll
            for (int i = 0; i < 4; i++)
#pragma unroll
                for (int j = 0; j < 4; j++) sacc[i][j] = fmaf(a[i], b[j], sacc[i][j]);
        }
        __syncthreads();  // done reading Ks; zc now visible to all

        float zj[4];
#pragma unroll
        for (int j = 0; j < 4; j++) zj[j] = zc[tx * 4 + j];

        float rmax[4];
#pragma unroll
        for (int i = 0; i < 4; i++) {
            const int qr = q0 + ty * 4 + i;
            const float4 mk = *reinterpret_cast<const float4*>(
                mask + (size_t)qr * SQ + kt * 64 + tx * 4);
            sacc[i][0] = (sacc[i][0] + mk.x * zj[0]) * zj[0];
            sacc[i][1] = (sacc[i][1] + mk.y * zj[1]) * zj[1];
            sacc[i][2] = (sacc[i][2] + mk.z * zj[2]) * zj[2];
            sacc[i][3] = (sacc[i][3] + mk.w * zj[3]) * zj[3];

            float4 o = make_float4(sacc[i][0], sacc[i][1], sacc[i][2], sacc[i][3]);
            *reinterpret_cast<float4*>(
                qk_out + ((size_t)h * SQ + qr) * SQ + kt * 64 + tx * 4) = o;

            float mx = fmaxf(fmaxf(sacc[i][0], sacc[i][1]), fmaxf(sacc[i][2], sacc[i][3]));
#pragma unroll
            for (int o2 = 8; o2; o2 >>= 1)
                mx = fmaxf(mx, __shfl_xor_sync(0xffffffffu, mx, o2));
            rmax[i] = mx;
        }

        // Online softmax update (stats replicated across the 16-lane group)
        float fsc[4];
#pragma unroll
        for (int i = 0; i < 4; i++) {
            const float mn = fmaxf(m_i[i], rmax[i]);
            fsc[i] = expf(m_i[i] - mn);   // 0 on first tile (m=-inf)
            m_i[i] = mn;
        }

#pragma unroll
        for (int i = 0; i < 4; i++) {
            float ssum = 0.f;
#pragma unroll
            for (int j = 0; j < 4; j++) {
                const float p = expf(sacc[i][j] - m_i[i]);
                Ks[(ty * 4 + i) * 65 + tx * 4 + j] = p;   // reuse K buffer for P
                ssum += p;
            }
#pragma unroll
            for (int o2 = 8; o2; o2 >>= 1)
                ssum += __shfl_xor_sync(0xffffffffu, ssum, o2);
            l_i[i] = l_i[i] * fsc[i] + ssum;
#pragma unroll
            for (int j = 0; j < 4; j++) acc[i][j] *= fsc[i];
        }
        __syncthreads();  // P fully written

        // acc += P * V
#pragma unroll 4
        for (int kk = 0; kk < 64; kk++) {
            float p[4], v[4];
#pragma unroll
            for (int i = 0; i < 4; i++) p[i] = Ks[(ty * 4 + i) * 65 + kk];
#pragma unroll
            for (int j = 0; j < 4; j++) v[j] = Vs[kk * 65 + tx * 4 + j];
#pragma unroll
            for (int i = 0; i < 4; i++)
#pragma unroll
                for (int j = 0; j < 4; j++) acc[i][j] = fmaf(p[i], v[j], acc[i][j]);
        }
    }

    // Write wv back in [S, D] layout (transposed merge of heads)
#pragma unroll
    for (int i = 0; i < 4; i++) {
        const int qr = q0 + ty * 4 + i;
        const float inv = 1.f / l_i[i];
        float4 o = make_float4(acc[i][0] * inv, acc[i][1] * inv,
                               acc[i][2] * inv, acc[i][3] * inv);
        *reinterpret_cast<float4*>(g_wv + (size_t)qr * DM + h * HD + tx * 4) = o;
    }
}

// ---------------------------------------------------------------------------
extern "C" void kernel_launch(void* const* d_in, const int* in_sizes, int n_in,
                              void* d_out, int out_size)
{
    const float* x    = (const float*)d_in[0];
    const float* mask = (const float*)d_in[1];
    const float* Wq   = (const float*)d_in[2];
    const float* bq   = (const float*)d_in[3];
    const float* Wk   = (const float*)d_in[4];
    const float* Wv   = (const float*)d_in[5];
    const float* bv   = (const float*)d_in[6];
    const float* Wo   = (const float*)d_in[7];
    const float* bo   = (const float*)d_in[8];
    const float* Zf   = (const float*)d_in[9];
    const float* invf = (const float*)d_in[10];

    float* out = (float*)d_out;                       // [2048, 1024]
    float* qk  = out + (size_t)SQ * DM;               // [16, 2048, 2048]

    float *qptr, *kptr, *vptr, *wvptr;
    cudaGetSymbolAddress((void**)&qptr, g_q);
    cudaGetSymbolAddress((void**)&kptr, g_k);
    cudaGetSymbolAddress((void**)&vptr, g_v);
    cudaGetSymbolAddress((void**)&wvptr, g_wv);

    const dim3 gg(DM / 64, SQ / 64);   // (16, 32)

    // q, k, v projections (k has no bias)
    gemm_nt<1><<<gg, 256>>>(x, Wq, bq, qptr, SQ, DM, DM);
    gemm_nt<1><<<gg, 256>>>(x, Wk, (const float*)nullptr, kptr, SQ, DM, DM);
    gemm_nt<1><<<gg, 256>>>(x, Wv, bv, vptr, SQ, DM, DM);

    // RoPE + scale fold on q and k
    rope_kernel<<<2 * NH * SQ, 32>>>(invf);

    // Attention (writes qk output and g_wv)
    const int smem_bytes = (3 * 64 * 65 + 64) * (int)sizeof(float);  // 50176
    cudaFuncSetAttribute(attn_kernel, cudaFuncAttributeMaxDynamicSharedMemorySize,
                         smem_bytes);
    attn_kernel<<<dim3(SQ / 64, NH), 256, smem_bytes>>>(mask, Zf, qk);

    // Output projection
    gemm_nt<0><<<gg, 256>>>(wvptr, Wo, bo, out, SQ, DM, DM);
}

// round 3
// speedup vs baseline: 1.0061x; 1.0061x over previous
#include <cuda_runtime.h>
#include <math.h>

#define SQ 2048
#define DM 1024
#define NH 16
#define HD 64

typedef unsigned long long u64;

// Scratch (allocation-free: device globals)
static __device__ float g_q[NH * SQ * HD];
static __device__ float g_k[NH * SQ * HD];
static __device__ float g_v[NH * SQ * HD];
static __device__ float g_wv[SQ * DM];
static __device__ float g_cos[SQ * 32];
static __device__ float g_sin[SQ * 32];

// ---------------- f32x2 packed helpers ----------------
__device__ __forceinline__ u64 pk2(float lo, float hi) {
    u64 r;
    asm("mov.b64 %0, {%1, %2};" : "=l"(r) : "r"(__float_as_uint(lo)), "r"(__float_as_uint(hi)));
    return r;
}
__device__ __forceinline__ float2 unpk(u64 v) {
    unsigned a, b;
    asm("mov.b64 {%0, %1}, %2;" : "=r"(a), "=r"(b) : "l"(v));
    return make_float2(__uint_as_float(a), __uint_as_float(b));
}
__device__ __forceinline__ void fma2(u64& d, u64 a, u64 b) {
    asm("fma.rn.f32x2 %0, %1, %2, %0;" : "+l"(d) : "l"(a), "l"(b));
}
__device__ __forceinline__ u64 mul2(u64 a, u64 b) {
    u64 d;
    asm("mul.rn.f32x2 %0, %1, %2;" : "=l"(d) : "l"(a), "l"(b));
    return d;
}

// ---------------------------------------------------------------------------
// RoPE cos/sin table, fp64-accurate. idx = s*32 + j.
// ---------------------------------------------------------------------------
__global__ void rope_table(const float* __restrict__ inv_freq)
{
    const int idx = blockIdx.x * 256 + threadIdx.x;   // 0..65535
    const int s = idx >> 5;
    const int j = idx & 31;
    const double f = (double)s * (double)inv_freq[j];
    g_cos[idx] = (float)cos(f);
    g_sin[idx] = (float)sin(f);
}

// ---------------------------------------------------------------------------
// GEMM core: 128x128 tile, BK=16, 256 threads, 8x8 per thread, f32x2 packed,
// double-buffered. A duplicated+transposed in smem, W transposed in smem.
// smem layout: sA[2][16][256] (32KB) then sW[2][16][128] (16KB).
// ---------------------------------------------------------------------------
__device__ __forceinline__ void gemm_core(
    const float* __restrict__ A, const float* __restrict__ W,
    int m0, int n0, int K, float* sm, u64 acc2[8][4], int tid)
{
    float* sA = sm;            // [2][16][256]
    float* sW = sm + 8192;     // [2][16][128]

    const int lm = tid & 127;
    const int lk = tid >> 7;         // 0..1
    const int tx = tid & 15;
    const int ty = tid >> 4;

#pragma unroll
    for (int i = 0; i < 8; i++)
#pragma unroll
        for (int j = 0; j < 4; j++) acc2[i][j] = 0ULL;

    float4 ar[2], wr[2];
    const int KT = K / 16;

    // prologue load (tile 0)
#pragma unroll
    for (int L = 0; L < 2; L++) {
        const int kg = lk * 2 + L;
        ar[L] = *reinterpret_cast<const float4*>(A + (size_t)(m0 + lm) * K + kg * 4);
        wr[L] = *reinterpret_cast<const float4*>(W + (size_t)(n0 + lm) * K + kg * 4);
    }

    int buf = 0;
    for (int t = 0; t < KT; t++) {
        // store regs -> smem[buf]
#pragma unroll
        for (int L = 0; L < 2; L++) {
            const int kg = lk * 2 + L;
            const float a0 = ar[L].x, a1 = ar[L].y, a2 = ar[L].z, a3 = ar[L].w;
            float* pa = sA + (size_t)(buf * 16 + kg * 4) * 256 + 2 * lm;
            *reinterpret_cast<float2*>(pa + 0 * 256) = make_float2(a0, a0);
            *reinterpret_cast<float2*>(pa + 1 * 256) = make_float2(a1, a1);
            *reinterpret_cast<float2*>(pa + 2 * 256) = make_float2(a2, a2);
            *reinterpret_cast<float2*>(pa + 3 * 256) = make_float2(a3, a3);
            float* pw = sW + (size_t)(buf * 16 + kg * 4) * 128 + lm;
            pw[0 * 128] = wr[L].x; pw[1 * 128] = wr[L].y;
            pw[2 * 128] = wr[L].z; pw[3 * 128] = wr[L].w;
        }
        __syncthreads();

        if (t + 1 < KT) {
            const int k0 = (t + 1) * 16;
#pragma unroll
            for (int L = 0; L < 2; L++) {
                const int kg = lk * 2 + L;
                ar[L] = *reinterpret_cast<const float4*>(A + (size_t)(m0 + lm) * K + k0 + kg * 4);
                wr[L] = *reinterpret_cast<const float4*>(W + (size_t)(n0 + lm) * K + k0 + kg * 4);
            }
        }

#pragma unroll
        for (int kk = 0; kk < 16; kk++) {
            const u64* ap = reinterpret_cast<const u64*>(sA + (size_t)(buf * 16 + kk) * 256) + ty * 8;
            const ulonglong2 A0 = *reinterpret_cast<const ulonglong2*>(ap + 0);
            const ulonglong2 A1 = *reinterpret_cast<const ulonglong2*>(ap + 2);
            const ulonglong2 A2 = *reinterpret_cast<const ulonglong2*>(ap + 4);
            const ulonglong2 A3 = *reinterpret_cast<const ulonglong2*>(ap + 6);
            u64 aa[8] = {A0.x, A0.y, A1.x, A1.y, A2.x, A2.y, A3.x, A3.y};
            const u64* bp = reinterpret_cast<const u64*>(sW + (size_t)(buf * 16 + kk) * 128) + tx * 4;
            const ulonglong2 B0 = *reinterpret_cast<const ulonglong2*>(bp + 0);
            const ulonglong2 B1 = *reinterpret_cast<const ulonglong2*>(bp + 2);
            u64 b2[4] = {B0.x, B0.y, B1.x, B1.y};
#pragma unroll
            for (int i = 0; i < 8; i++)
#pragma unroll
                for (int j = 0; j < 4; j++) fma2(acc2[i][j], aa[i], b2[j]);
        }
        buf ^= 1;
        __syncthreads();
    }
}

// ---------------------------------------------------------------------------
// Fused QKV GEMM: z=0 -> q (bias bq, rope), z=1 -> k (no bias, rope),
// z=2 -> v (bias bv). Output in head layout [h][s][d].
// ---------------------------------------------------------------------------
__global__ void __launch_bounds__(256, 2) qkv_gemm(
    const float* __restrict__ x,
    const float* __restrict__ Wq, const float* __restrict__ Wk,
    const float* __restrict__ Wv,
    const float* __restrict__ bq, const float* __restrict__ bv)
{
    extern __shared__ float smem[];
    const int tid = threadIdx.x;
    const int z = blockIdx.z;
    const int m0 = blockIdx.y * 128;
    const int n0 = blockIdx.x * 128;

    const float* W = (z == 0) ? Wq : (z == 1) ? Wk : Wv;
    const float* bias = (z == 0) ? bq : (z == 2) ? bv : nullptr;
    float* out = (z == 0) ? g_q : (z == 1) ? g_k : g_v;

    u64 acc2[8][4];
    gemm_core(x, W, m0, n0, DM, smem, acc2, tid);

    const int tx = tid & 15;
    const int ty = tid >> 4;
    const float rsc = 0.35355339059327373f;   // 64^(-1/4)

#pragma unroll
    for (int i = 0; i < 8; i++) {
        const int m = m0 + ty * 8 + i;
        float vals[8];
#pragma unroll
        for (int j = 0; j < 4; j++) {
            const float2 u = unpk(acc2[i][j]);
            vals[2 * j] = u.x; vals[2 * j + 1] = u.y;
        }
        if (bias) {
#pragma unroll
            for (int o = 0; o < 8; o++) vals[o] += bias[n0 + tx * 8 + o];
        }
#pragma unroll
        for (int p = 0; p < 4; p++) {
            const int n = n0 + tx * 8 + 2 * p;
            const int h = n >> 6;
            const int d = n & 63;
            float* dst = out + ((size_t)h * SQ + m) * HD + d;
            if (z < 2) {
                const int pi = d >> 1;
                const float c = g_cos[m * 32 + pi];
                const float s = g_sin[m * 32 + pi];
                const float a = vals[2 * p], b = vals[2 * p + 1];
                *reinterpret_cast<float2*>(dst) =
                    make_float2(rsc * (a * c - b * s), rsc * (a * s + b * c));
            } else {
                *reinterpret_cast<float2*>(dst) = make_float2(vals[2 * p], vals[2 * p + 1]);
            }
        }
    }
}

// ---------------------------------------------------------------------------
// Output projection: out = g_wv @ Wo^T + bo, row-major [S, D]
// ---------------------------------------------------------------------------
__global__ void __launch_bounds__(256, 2) out_gemm(
    const float* __restrict__ Wo, const float* __restrict__ bo,
    float* __restrict__ C)
{
    extern __shared__ float smem[];
    const int tid = threadIdx.x;
    const int m0 = blockIdx.y * 128;
    const int n0 = blockIdx.x * 128;

    u64 acc2[8][4];
    gemm_core(g_wv, Wo, m0, n0, DM, smem, acc2, tid);

    const int tx = tid & 15;
    const int ty = tid >> 4;
#pragma unroll
    for (int i = 0; i < 8; i++) {
        const int m = m0 + ty * 8 + i;
#pragma unroll
        for (int j = 0; j < 4; j++) {
            const int n = n0 + tx * 8 + 2 * j;
            float2 u = unpk(acc2[i][j]);
            u.x += bo[n]; u.y += bo[n + 1];
            *reinterpret_cast<float2*>(C + (size_t)m * DM + n) = u;
        }
    }
}

// ---------------------------------------------------------------------------
// Attention: 64 q-rows x 64 k-cols tiles, flash online softmax, writes
// pre-softmax qk and g_wv. Packed f32x2 inner GEMMs:
//   S = Q K^T : Q duplicated+transposed (Qt2), K transposed (Kt)
//   O += P V  : P duplicated (P2), V natural row-major (Vs)
// smem: Qt2[64][128] | Kt[64][64] | Vs[64][64] | P2[64][128] | zc[64]
// ---------------------------------------------------------------------------
__global__ void __launch_bounds__(256, 2) attn_kernel(
    const float* __restrict__ mask, const float* __restrict__ Zf,
    float* __restrict__ qk_out)
{
    extern __shared__ float sm[];
    float* Qt2 = sm;                    // 64*128
    float* Kt  = sm + 64 * 128;         // 64*64
    float* Vs  = Kt + 64 * 64;          // 64*64
    float* P2  = Vs + 64 * 64;          // 64*128
    float* zc  = P2 + 64 * 128;         // 64

    const int tid = threadIdx.x;
    const int tx = tid & 15;
    const int ty = tid >> 4;
    const int q0 = blockIdx.x * 64;
    const int h = blockIdx.y;

    const float zfac = fminf(fmaxf(log1pf(expf(Zf[0])), 1e-5f), 1e-4f);

    const float* qg = g_q + ((size_t)h * SQ + q0) * HD;
    const float* kg = g_k + (size_t)h * SQ * HD;
    const float* vg = g_v + (size_t)h * SQ * HD;

    // Load Q -> Qt2 (duplicated, transposed): Qt2[d][2m],[2m+1] = Q[m][d]
    {
        const int m = tid & 63;
        const int g = tid >> 6;    // 0..3
#pragma unroll
        for (int L = 0; L < 4; L++) {
            const int dg = g * 4 + L;  // 0..15
            const float4 v = *reinterpret_cast<const float4*>(qg + m * HD + dg * 4);
            float* p = Qt2 + (size_t)(dg * 4) * 128 + 2 * m;
            *reinterpret_cast<float2*>(p + 0 * 128) = make_float2(v.x, v.x);
            *reinterpret_cast<float2*>(p + 1 * 128) = make_float2(v.y, v.y);
            *reinterpret_cast<float2*>(p + 2 * 128) = make_float2(v.z, v.z);
            *reinterpret_cast<float2*>(p + 3 * 128) = make_float2(v.w, v.w);
        }
    }

    u64 acc2[4][2];
    float m_i[4], l_i[4];
#pragma unroll
    for (int i = 0; i < 4; i++) {
        m_i[i] = -INFINITY; l_i[i] = 0.f;
        acc2[i][0] = 0ULL; acc2[i][1] = 0ULL;
    }

    for (int kt = 0; kt < SQ / 64; kt++) {
        __syncthreads();  // prev P2/Vs reads done (and Qt2 visible on iter 0)

        const float* kgt = kg + (size_t)kt * 64 * HD;
        const float* vgt = vg + (size_t)kt * 64 * HD;
        {
            const int m = tid & 63;
            const int g = tid >> 6;
#pragma unroll
            for (int L = 0; L < 4; L++) {
                const int dg = g * 4 + L;
                const float4 kv = *reinterpret_cast<const float4*>(kgt + m * HD + dg * 4);
                Kt[(dg * 4 + 0) * 64 + m] = kv.x;
                Kt[(dg * 4 + 1) * 64 + m] = kv.y;
                Kt[(dg * 4 + 2) * 64 + m] = kv.z;
                Kt[(dg * 4 + 3) * 64 + m] = kv.w;
                const float4 vv = *reinterpret_cast<const float4*>(vgt + m * HD + dg * 4);
                *reinterpret_cast<float4*>(Vs + m * 64 + dg * 4) = vv;
            }
        }
        __syncthreads();
        if (tid < 64) zc[tid] = (Kt[tid] == 0.f) ? zfac : 1.f;

        // S = Q K^T (packed over key pairs)
        u64 s2[4][2];
#pragma unroll
        for (int i = 0; i < 4; i++) { s2[i][0] = 0ULL; s2[i][1] = 0ULL; }

#pragma unroll 4
        for (int kk = 0; kk < HD; kk++) {
            const u64* ap = reinterpret_cast<const u64*>(Qt2 + (size_t)kk * 128) + ty * 4;
            const ulonglong2 A0 = *reinterpret_cast<const ulonglong2*>(ap + 0);
            const ulonglong2 A1 = *reinterpret_cast<const ulonglong2*>(ap + 2);
            const u64 aa[4] = {A0.x, A0.y, A1.x, A1.y};
            const u64* bp = reinterpret_cast<const u64*>(Kt + (size_t)kk * 64) + tx * 2;
            const ulonglong2 B = *reinterpret_cast<const ulonglong2*>(bp);
#pragma unroll
            for (int i = 0; i < 4; i++) {
                fma2(s2[i][0], aa[i], B.x);
                fma2(s2[i][1], aa[i], B.y);
            }
        }
        __syncthreads();  // Kt reads done; zc visible

        float sacc[4][4];
#pragma unroll
        for (int i = 0; i < 4; i++) {
            const float2 u0 = unpk(s2[i][0]);
            const float2 u1 = unpk(s2[i][1]);
            sacc[i][0] = u0.x; sacc[i][1] = u0.y;
            sacc[i][2] = u1.x; sacc[i][3] = u1.y;
        }

        float zj[4];
#pragma unroll
        for (int j = 0; j < 4; j++) zj[j] = zc[tx * 4 + j];

        float rmax[4];
#pragma unroll
        for (int i = 0; i < 4; i++) {
            const int qr = q0 + ty * 4 + i;
            const float4 mk = *reinterpret_cast<const float4*>(
                mask + (size_t)qr * SQ + kt * 64 + tx * 4);
            sacc[i][0] = (sacc[i][0] + mk.x * zj[0]) * zj[0];
            sacc[i][1] = (sacc[i][1] + mk.y * zj[1]) * zj[1];
            sacc[i][2] = (sacc[i][2] + mk.z * zj[2]) * zj[2];
            sacc[i][3] = (sacc[i][3] + mk.w * zj[3]) * zj[3];

            *reinterpret_cast<float4*>(
                qk_out + ((size_t)h * SQ + qr) * SQ + kt * 64 + tx * 4) =
                make_float4(sacc[i][0], sacc[i][1], sacc[i][2], sacc[i][3]);

            float mx = fmaxf(fmaxf(sacc[i][0], sacc[i][1]), fmaxf(sacc[i][2], sacc[i][3]));
#pragma unroll
            for (int o2 = 8; o2; o2 >>= 1)
                mx = fmaxf(mx, __shfl_xor_sync(0xffffffffu, mx, o2));
            rmax[i] = mx;
        }

        // online softmax update
#pragma unroll
        for (int i = 0; i < 4; i++) {
            const float mn = fmaxf(m_i[i], rmax[i]);
            const float fsc = __expf(m_i[i] - mn);   // 0 on first tile
            m_i[i] = mn;

            float ssum = 0.f;
#pragma unroll
            for (int j = 0; j < 4; j++) {
                const float p = __expf(sacc[i][j] - mn);
                *reinterpret_cast<float2*>(
                    P2 + (size_t)(ty * 4 + i) * 128 + 2 * (tx * 4 + j)) = make_float2(p, p);
                ssum += p;
            }
#pragma unroll
            for (int o2 = 8; o2; o2 >>= 1)
                ssum += __shfl_xor_sync(0xffffffffu, ssum, o2);
            l_i[i] = l_i[i] * fsc + ssum;

            const u64 f2 = pk2(fsc, fsc);
            acc2[i][0] = mul2(acc2[i][0], f2);
            acc2[i][1] = mul2(acc2[i][1], f2);
        }
        __syncthreads();  // P2 fully written

        // O += P V (packed over value-dim pairs)
#pragma unroll 4
        for (int kk = 0; kk < 64; kk++) {
            u64 pp[4];
#pragma unroll
            for (int i = 0; i < 4; i++)
                pp[i] = *reinterpret_cast<const u64*>(P2 + (size_t)(ty * 4 + i) * 128 + 2 * kk);
            const u64* vp = reinterpret_cast<const u64*>(Vs + (size_t)kk * 64) + tx * 2;
            const ulonglong2 V = *reinterpret_cast<const ulonglong2*>(vp);
#pragma unroll
            for (int i = 0; i < 4; i++) {
                fma2(acc2[i][0], pp[i], V.x);
                fma2(acc2[i][1], pp[i], V.y);
            }
        }
    }

    // write wv in [S, D] layout
#pragma unroll
    for (int i = 0; i < 4; i++) {
        const int qr = q0 + ty * 4 + i;
        const float inv = 1.f / l_i[i];
        const float2 u0 = unpk(acc2[i][0]);
        const float2 u1 = unpk(acc2[i][1]);
        *reinterpret_cast<float4*>(g_wv + (size_t)qr * DM + h * HD + tx * 4) =
            make_float4(u0.x * inv, u0.y * inv, u1.x * inv, u1.y * inv);
    }
}

// ---------------------------------------------------------------------------
extern "C" void kernel_launch(void* const* d_in, const int* in_sizes, int n_in,
                              void* d_out, int out_size)
{
    const float* x    = (const float*)d_in[0];
    const float* mask = (const float*)d_in[1];
    const float* Wq   = (const float*)d_in[2];
    const float* bq   = (const float*)d_in[3];
    const float* Wk   = (const float*)d_in[4];
    const float* Wv   = (const float*)d_in[5];
    const float* bv   = (const float*)d_in[6];
    const float* Wo   = (const float*)d_in[7];
    const float* bo   = (const float*)d_in[8];
    const float* Zf   = (const float*)d_in[9];
    const float* invf = (const float*)d_in[10];

    float* out = (float*)d_out;                       // [2048, 1024]
    float* qk  = out + (size_t)SQ * DM;               // [16, 2048, 2048]

    const int gemm_smem = 12288 * (int)sizeof(float);   // 48 KB
    const int attn_smem = (64 * 128 + 64 * 64 + 64 * 64 + 64 * 128 + 64) * (int)sizeof(float);

    static bool attrs_set = false;
    if (!attrs_set) {
        cudaFuncSetAttribute(qkv_gemm, cudaFuncAttributeMaxDynamicSharedMemorySize, gemm_smem);
        cudaFuncSetAttribute(out_gemm, cudaFuncAttributeMaxDynamicSharedMemorySize, gemm_smem);
        cudaFuncSetAttribute(attn_kernel, cudaFuncAttributeMaxDynamicSharedMemorySize, attn_smem);
        attrs_set = true;
    }

    // RoPE table
    rope_table<<<256, 256>>>(invf);

    // Fused QKV projections + RoPE + scale (head layout outputs)
    qkv_gemm<<<dim3(DM / 128, SQ / 128, 3), 256, gemm_smem>>>(x, Wq, Wk, Wv, bq, bv);

    // Attention (writes qk output and g_wv)
    attn_kernel<<<dim3(SQ / 64, NH), 256, attn_smem>>>(mask, Zf, qk);

    // Output projection
    out_gemm<<<dim3(DM / 128, SQ / 128), 256, gemm_smem>>>(Wo, bo, out);
}

// round 4
// speedup vs baseline: 1.5212x; 1.5119x over previous
#include <cuda_runtime.h>
#include <math.h>

#define SQ 2048
#define DM 1024
#define NH 16
#define HD 64

// Scratch (allocation-free: device globals)
static __device__ float g_q[NH * SQ * HD];
static __device__ float g_k[NH * SQ * HD];
static __device__ float g_v[NH * SQ * HD];
static __device__ float g_wv[SQ * DM];
static __device__ float g_cos[SQ * 32];
static __device__ float g_sin[SQ * 32];

// ---------------- tf32 helpers ----------------
__device__ __forceinline__ unsigned f2tf(float x) {
    unsigned r;
    asm("cvt.rna.tf32.f32 %0, %1;" : "=r"(r) : "f"(x));
    return r;
}
// split x into (hi, lo) tf32 pair stored as float bit patterns
__device__ __forceinline__ float2 splt(float x) {
    unsigned h = f2tf(x);
    float hf = __uint_as_float(h);
    unsigned l = f2tf(x - hf);
    return make_float2(hf, __uint_as_float(l));
}

__device__ __forceinline__ void mma8(float& c0, float& c1, float& c2, float& c3,
                                     unsigned a0, unsigned a1, unsigned a2, unsigned a3,
                                     unsigned b0, unsigned b1) {
    asm volatile(
        "mma.sync.aligned.m16n8k8.row.col.f32.tf32.tf32.f32 "
        "{%0,%1,%2,%3},{%4,%5,%6,%7},{%8,%9},{%0,%1,%2,%3};"
        : "+f"(c0), "+f"(c1), "+f"(c2), "+f"(c3)
        : "r"(a0), "r"(a1), "r"(a2), "r"(a3), "r"(b0), "r"(b1));
}

// 3-term split mma: c += (ah+al)*(bh+bl) ~ ah*bh + ah*bl + al*bh
__device__ __forceinline__ void mma3(float* c,
                                     const unsigned ah[4], const unsigned al[4],
                                     unsigned bh0, unsigned bh1,
                                     unsigned bl0, unsigned bl1) {
    mma8(c[0], c[1], c[2], c[3], ah[0], ah[1], ah[2], ah[3], bh0, bh1);
    mma8(c[0], c[1], c[2], c[3], ah[0], ah[1], ah[2], ah[3], bl0, bl1);
    mma8(c[0], c[1], c[2], c[3], al[0], al[1], al[2], al[3], bh0, bh1);
}

// ---------------------------------------------------------------------------
// RoPE cos/sin table, fp64-accurate. idx = s*32 + j.
// ---------------------------------------------------------------------------
__global__ void rope_table(const float* __restrict__ inv_freq)
{
    const int idx = blockIdx.x * 256 + threadIdx.x;   // 0..65535
    const int s = idx >> 5;
    const int j = idx & 31;
    const double f = (double)s * (double)inv_freq[j];
    g_cos[idx] = (float)cos(f);
    g_sin[idx] = (float)sin(f);
}

// ---------------------------------------------------------------------------
// Projection GEMM core (tf32 3x): C = A[M,K] * W[N,K]^T
// CTA 128x128, BK=16, 256 threads = 8 warps (2m x 4n), warp tile 64x32.
// smem: (hi,lo) float2, row stride 20 float2 (pad: 20 % 16 == 4 -> conflict-free).
// acc[mt 0..3][nt 0..3][4]
// ---------------------------------------------------------------------------
#define PJ_STR 20
#define PJ_BUF 2560   // 128*20 float2 per matrix per buffer

__device__ __forceinline__ void proj_core(
    const float* __restrict__ A, const float* __restrict__ W,
    int m0, int n0, float2* sm2, float acc[4][4][4], int tid)
{
    const int lane = tid & 31;
    const int wid = tid >> 5;
    const int g = lane >> 2;
    const int t = lane & 3;
    const int wm = (wid & 1) * 64;
    const int wn = (wid >> 1) * 32;

    const int lr = tid >> 1;             // 0..127
    const int lk = (tid & 1) * 8;        // 0 or 8

#pragma unroll
    for (int mt = 0; mt < 4; mt++)
#pragma unroll
        for (int nt = 0; nt < 4; nt++)
#pragma unroll
            for (int r = 0; r < 4; r++) acc[mt][nt][r] = 0.f;

    const float* Ar = A + (size_t)(m0 + lr) * DM;
    const float* Wr = W + (size_t)(n0 + lr) * DM;

    float4 fa0 = *reinterpret_cast<const float4*>(Ar + lk);
    float4 fa1 = *reinterpret_cast<const float4*>(Ar + lk + 4);
    float4 fw0 = *reinterpret_cast<const float4*>(Wr + lk);
    float4 fw1 = *reinterpret_cast<const float4*>(Wr + lk + 4);

    int buf = 0;
    for (int kt = 0; kt < DM / 16; kt++) {
        float2* sA = sm2 + buf * (2 * PJ_BUF);
        float2* sW = sA + PJ_BUF;
        {
            float2* pa = sA + lr * PJ_STR + lk;
            pa[0] = splt(fa0.x); pa[1] = splt(fa0.y); pa[2] = splt(fa0.z); pa[3] = splt(fa0.w);
            pa[4] = splt(fa1.x); pa[5] = splt(fa1.y); pa[6] = splt(fa1.z); pa[7] = splt(fa1.w);
            float2* pw = sW + lr * PJ_STR + lk;
            pw[0] = splt(fw0.x); pw[1] = splt(fw0.y); pw[2] = splt(fw0.z); pw[3] = splt(fw0.w);
            pw[4] = splt(fw1.x); pw[5] = splt(fw1.y); pw[6] = splt(fw1.z); pw[7] = splt(fw1.w);
        }
        __syncthreads();

        if (kt + 1 < DM / 16) {
            const int k0 = (kt + 1) * 16;
            fa0 = *reinterpret_cast<const float4*>(Ar + k0 + lk);
            fa1 = *reinterpret_cast<const float4*>(Ar + k0 + lk + 4);
            fw0 = *reinterpret_cast<const float4*>(Wr + k0 + lk);
            fw1 = *reinterpret_cast<const float4*>(Wr + k0 + lk + 4);
        }

#pragma unroll
        for (int ks = 0; ks < 2; ks++) {
            unsigned ah[4][4], al[4][4];
#pragma unroll
            for (int mt = 0; mt < 4; mt++) {
                const int r0 = wm + mt * 16 + g;
                float2 v0 = sA[r0 * PJ_STR + ks * 8 + t];
                float2 v1 = sA[(r0 + 8) * PJ_STR + ks * 8 + t];
                float2 v2 = sA[r0 * PJ_STR + ks * 8 + t + 4];
                float2 v3 = sA[(r0 + 8) * PJ_STR + ks * 8 + t + 4];
                ah[mt][0] = __float_as_uint(v0.x); al[mt][0] = __float_as_uint(v0.y);
                ah[mt][1] = __float_as_uint(v1.x); al[mt][1] = __float_as_uint(v1.y);
                ah[mt][2] = __float_as_uint(v2.x); al[mt][2] = __float_as_uint(v2.y);
                ah[mt][3] = __float_as_uint(v3.x); al[mt][3] = __float_as_uint(v3.y);
            }
#pragma unroll
            for (int nt = 0; nt < 4; nt++) {
                const int nrow = wn + nt * 8 + g;
                float2 b0 = sW[nrow * PJ_STR + ks * 8 + t];
                float2 b1 = sW[nrow * PJ_STR + ks * 8 + t + 4];
                unsigned bh0 = __float_as_uint(b0.x), bl0 = __float_as_uint(b0.y);
                unsigned bh1 = __float_as_uint(b1.x), bl1 = __float_as_uint(b1.y);
#pragma unroll
                for (int mt = 0; mt < 4; mt++)
                    mma3(acc[mt][nt], ah[mt], al[mt], bh0, bh1, bl0, bl1);
            }
        }
        buf ^= 1;
        __syncthreads();
    }
}

// ---------------------------------------------------------------------------
// Fused QKV GEMM + RoPE + scale, head layout output.
// ---------------------------------------------------------------------------
__global__ void __launch_bounds__(256) qkv_gemm(
    const float* __restrict__ x,
    const float* __restrict__ Wq, const float* __restrict__ Wk,
    const float* __restrict__ Wv,
    const float* __restrict__ bq, const float* __restrict__ bv)
{
    extern __shared__ float2 sm2[];
    const int tid = threadIdx.x;
    const int z = blockIdx.z;
    const int m0 = blockIdx.y * 128;
    const int n0 = blockIdx.x * 128;

    const float* W = (z == 0) ? Wq : (z == 1) ? Wk : Wv;
    const float* bias = (z == 0) ? bq : (z == 2) ? bv : nullptr;
    float* out = (z == 0) ? g_q : (z == 1) ? g_k : g_v;

    float acc[4][4][4];
    proj_core(x, W, m0, n0, sm2, acc, tid);

    const int lane = tid & 31;
    const int wid = tid >> 5;
    const int g = lane >> 2;
    const int t = lane & 3;
    const int wm = (wid & 1) * 64;
    const int wn = (wid >> 1) * 32;
    const float rsc = 0.35355339059327373f;   // 64^(-1/4)

#pragma unroll
    for (int mt = 0; mt < 4; mt++) {
#pragma unroll
        for (int nt = 0; nt < 4; nt++) {
            const int n = n0 + wn + nt * 8 + 2 * t;
            const int hh = n >> 6;
            const int d = n & 63;
            float b0v = bias ? bias[n] : 0.f;
            float b1v = bias ? bias[n + 1] : 0.f;
#pragma unroll
            for (int half = 0; half < 2; half++) {
                const int m = m0 + wm + mt * 16 + g + half * 8;
                float a = acc[mt][nt][half * 2 + 0] + b0v;
                float b = acc[mt][nt][half * 2 + 1] + b1v;
                float* dst = out + ((size_t)hh * SQ + m) * HD + d;
                if (z < 2) {
                    const int pi = d >> 1;
                    const float c = g_cos[m * 32 + pi];
                    const float s = g_sin[m * 32 + pi];
                    *reinterpret_cast<float2*>(dst) =
                        make_float2(rsc * (a * c - b * s), rsc * (a * s + b * c));
                } else {
                    *reinterpret_cast<float2*>(dst) = make_float2(a, b);
                }
            }
        }
    }
}

// ---------------------------------------------------------------------------
// Output projection: out = g_wv @ Wo^T + bo
// ---------------------------------------------------------------------------
__global__ void __launch_bounds__(256) out_gemm(
    const float* __restrict__ Wo, const float* __restrict__ bo,
    float* __restrict__ C)
{
    extern __shared__ float2 sm2[];
    const int tid = threadIdx.x;
    const int m0 = blockIdx.y * 128;
    const int n0 = blockIdx.x * 128;

    float acc[4][4][4];
    proj_core(g_wv, Wo, m0, n0, sm2, acc, tid);

    const int lane = tid & 31;
    const int wid = tid >> 5;
    const int g = lane >> 2;
    const int t = lane & 3;
    const int wm = (wid & 1) * 64;
    const int wn = (wid >> 1) * 32;

#pragma unroll
    for (int mt = 0; mt < 4; mt++) {
#pragma unroll
        for (int nt = 0; nt < 4; nt++) {
            const int n = n0 + wn + nt * 8 + 2 * t;
            const float b0v = bo[n], b1v = bo[n + 1];
#pragma unroll
            for (int half = 0; half < 2; half++) {
                const int m = m0 + wm + mt * 16 + g + half * 8;
                *reinterpret_cast<float2*>(C + (size_t)m * DM + n) =
                    make_float2(acc[mt][nt][half * 2 + 0] + b0v,
                                acc[mt][nt][half * 2 + 1] + b1v);
            }
        }
    }
}

// ---------------------------------------------------------------------------
// Attention (tf32 3x mma, flash online softmax, qk streamed to gmem).
// CTA: 1 head x 256 q rows. 8 warps x 32 rows each. 64-key tiles.
// smem: sQ[256][68] f2(hi,lo) | sK[64][68] | sV[64][68]   (strides % 16 == 4)
// ---------------------------------------------------------------------------
#define AQ_STR 68

__global__ void __launch_bounds__(256) attn_kernel(
    const float* __restrict__ mask, const float* __restrict__ Zf,
    float* __restrict__ qk_out)
{
    extern __shared__ float2 sm2[];
    float2* sQ = sm2;                 // 256*68
    float2* sK = sQ + 256 * AQ_STR;   // 64*68
    float2* sV = sK + 64 * AQ_STR;    // 64*68

    const int tid = threadIdx.x;
    const int lane = tid & 31;
    const int wid = tid >> 5;
    const int g = lane >> 2;
    const int t = lane & 3;
    const int wr = wid * 32;          // warp's q-row base within CTA
    const int h = blockIdx.y;
    const int q0 = blockIdx.x * 256;

    const float zfac = fminf(fmaxf(log1pf(expf(Zf[0])), 1e-5f), 1e-4f);

    // ---- load Q block (hi/lo split) ----
    {
        const float* qg = g_q + ((size_t)h * SQ + q0 + tid) * HD;
#pragma unroll
        for (int c4 = 0; c4 < 16; c4++) {
            float4 v = *reinterpret_cast<const float4*>(qg + c4 * 4);
            float2* p = sQ + tid * AQ_STR + c4 * 4;
            p[0] = splt(v.x); p[1] = splt(v.y); p[2] = splt(v.z); p[3] = splt(v.w);
        }
    }

    float ofr[2][8][4];
    float m_i[4], l_i[4];   // [mt*2 + half]
#pragma unroll
    for (int mt = 0; mt < 2; mt++)
#pragma unroll
        for (int nt = 0; nt < 8; nt++)
#pragma unroll
            for (int r = 0; r < 4; r++) ofr[mt][nt][r] = 0.f;
#pragma unroll
    for (int i = 0; i < 4; i++) { m_i[i] = -INFINITY; l_i[i] = 0.f; }

    const float2* mask2 = reinterpret_cast<const float2*>(mask);
    float2* qk2 = reinterpret_cast<float2*>(qk_out);

    for (int kt = 0; kt < SQ / 64; kt++) {
        __syncthreads();
        // ---- load K/V tiles ----
        {
            const float* kg = g_k + ((size_t)h * SQ + kt * 64) * HD;
            const float* vg = g_v + ((size_t)h * SQ + kt * 64) * HD;
#pragma unroll
            for (int i = 0; i < 4; i++) {
                const int idx = tid + i * 256;        // 0..1023
                const int row = idx >> 4;
                const int c4 = idx & 15;
                float4 kv = *reinterpret_cast<const float4*>(kg + row * HD + c4 * 4);
                float2* pk = sK + row * AQ_STR + c4 * 4;
                pk[0] = splt(kv.x); pk[1] = splt(kv.y); pk[2] = splt(kv.z); pk[3] = splt(kv.w);
                float4 vv = *reinterpret_cast<const float4*>(vg + row * HD + c4 * 4);
                float2* pv = sV + row * AQ_STR + c4 * 4;
                pv[0] = splt(vv.x); pv[1] = splt(vv.y); pv[2] = splt(vv.z); pv[3] = splt(vv.w);
            }
        }
        __syncthreads();

        // ---- S = Q K^T ----
        float sfr[2][8][4];
#pragma unroll
        for (int mt = 0; mt < 2; mt++)
#pragma unroll
            for (int nt = 0; nt < 8; nt++)
#pragma unroll
                for (int r = 0; r < 4; r++) sfr[mt][nt][r] = 0.f;

#pragma unroll
        for (int ks = 0; ks < 8; ks++) {
            unsigned qh[2][4], ql[2][4];
#pragma unroll
            for (int mt = 0; mt < 2; mt++) {
                const int r0 = wr + mt * 16 + g;
                float2 v0 = sQ[r0 * AQ_STR + ks * 8 + t];
                float2 v1 = sQ[(r0 + 8) * AQ_STR + ks * 8 + t];
                float2 v2 = sQ[r0 * AQ_STR + ks * 8 + t + 4];
                float2 v3 = sQ[(r0 + 8) * AQ_STR + ks * 8 + t + 4];
                qh[mt][0] = __float_as_uint(v0.x); ql[mt][0] = __float_as_uint(v0.y);
                qh[mt][1] = __float_as_uint(v1.x); ql[mt][1] = __float_as_uint(v1.y);
                qh[mt][2] = __float_as_uint(v2.x); ql[mt][2] = __float_as_uint(v2.y);
                qh[mt][3] = __float_as_uint(v3.x); ql[mt][3] = __float_as_uint(v3.y);
            }
#pragma unroll
            for (int nt = 0; nt < 8; nt++) {
                const int key = nt * 8 + g;
                float2 b0 = sK[key * AQ_STR + ks * 8 + t];
                float2 b1 = sK[key * AQ_STR + ks * 8 + t + 4];
                unsigned bh0 = __float_as_uint(b0.x), bl0 = __float_as_uint(b0.y);
                unsigned bh1 = __float_as_uint(b1.x), bl1 = __float_as_uint(b1.y);
#pragma unroll
                for (int mt = 0; mt < 2; mt++)
                    mma3(sfr[mt][nt], qh[mt], ql[mt], bh0, bh1, bl0, bl1);
            }
        }

        // ---- mask + zscale + qk write + row max ----
        float rmax[4];
#pragma unroll
        for (int i = 0; i < 4; i++) rmax[i] = -INFINITY;

#pragma unroll
        for (int nt = 0; nt < 8; nt++) {
            const int c0col = nt * 8 + 2 * t;
            float2 k0a = sK[c0col * AQ_STR];
            float2 k0b = sK[(c0col + 1) * AQ_STR];
            const float z0 = (k0a.x == 0.f && k0a.y == 0.f) ? zfac : 1.f;
            const float z1 = (k0b.x == 0.f && k0b.y == 0.f) ? zfac : 1.f;
#pragma unroll
            for (int mt = 0; mt < 2; mt++) {
#pragma unroll
                for (int half = 0; half < 2; half++) {
                    const int r = q0 + wr + mt * 16 + g + half * 8;
                    float2 mk = mask2[(size_t)r * 1024 + kt * 32 + nt * 4 + t];
                    float s0 = (sfr[mt][nt][half * 2 + 0] + mk.x * z0) * z0;
                    float s1 = (sfr[mt][nt][half * 2 + 1] + mk.y * z1) * z1;
                    qk2[((size_t)h * SQ + r) * 1024 + kt * 32 + nt * 4 + t] =
                        make_float2(s0, s1);
                    sfr[mt][nt][half * 2 + 0] = s0;
                    sfr[mt][nt][half * 2 + 1] = s1;
                    rmax[mt * 2 + half] = fmaxf(rmax[mt * 2 + half], fmaxf(s0, s1));
                }
            }
        }

        // ---- online softmax ----
        float fsc[4], psum[4];
#pragma unroll
        for (int i = 0; i < 4; i++) {
            float mx = rmax[i];
            mx = fmaxf(mx, __shfl_xor_sync(0xffffffffu, mx, 1));
            mx = fmaxf(mx, __shfl_xor_sync(0xffffffffu, mx, 2));
            const float mn = fmaxf(m_i[i], mx);
            fsc[i] = __expf(m_i[i] - mn);
            m_i[i] = mn;
            psum[i] = 0.f;
        }
#pragma unroll
        for (int mt = 0; mt < 2; mt++)
#pragma unroll
            for (int nt = 0; nt < 8; nt++) {
#pragma unroll
                for (int half = 0; half < 2; half++) {
                    const int i = mt * 2 + half;
                    float p0 = __expf(sfr[mt][nt][half * 2 + 0] - m_i[i]);
                    float p1 = __expf(sfr[mt][nt][half * 2 + 1] - m_i[i]);
                    sfr[mt][nt][half * 2 + 0] = p0;
                    sfr[mt][nt][half * 2 + 1] = p1;
                    psum[i] += p0 + p1;
                }
            }
#pragma unroll
        for (int i = 0; i < 4; i++) {
            float ps = psum[i];
            ps += __shfl_xor_sync(0xffffffffu, ps, 1);
            ps += __shfl_xor_sync(0xffffffffu, ps, 2);
            l_i[i] = l_i[i] * fsc[i] + ps;
        }
        // rescale O
#pragma unroll
        for (int mt = 0; mt < 2; mt++)
#pragma unroll
            for (int nt = 0; nt < 8; nt++) {
                ofr[mt][nt][0] *= fsc[mt * 2];
                ofr[mt][nt][1] *= fsc[mt * 2];
                ofr[mt][nt][2] *= fsc[mt * 2 + 1];
                ofr[mt][nt][3] *= fsc[mt * 2 + 1];
            }

        // ---- O += P V ----
        const int srcA = (lane & ~3) | (t >> 1);
        const int srcB = srcA + 2;
#pragma unroll
        for (int s = 0; s < 8; s++) {
            unsigned vbh0[8], vbl0[8], vbh1[8], vbl1[8];
#pragma unroll
            for (int nt = 0; nt < 8; nt++) {
                const int d = nt * 8 + g;
                float2 b0 = sV[(s * 8 + t) * AQ_STR + d];
                float2 b1 = sV[(s * 8 + t + 4) * AQ_STR + d];
                vbh0[nt] = __float_as_uint(b0.x); vbl0[nt] = __float_as_uint(b0.y);
                vbh1[nt] = __float_as_uint(b1.x); vbl1[nt] = __float_as_uint(b1.y);
            }
#pragma unroll
            for (int mt = 0; mt < 2; mt++) {
                const float c0 = sfr[mt][s][0], c1 = sfr[mt][s][1];
                const float c2 = sfr[mt][s][2], c3 = sfr[mt][s][3];
                float x0 = __shfl_sync(0xffffffffu, c0, srcA);
                float x1 = __shfl_sync(0xffffffffu, c1, srcA);
                float y0 = __shfl_sync(0xffffffffu, c2, srcA);
                float y1 = __shfl_sync(0xffffffffu, c3, srcA);
                float x0b = __shfl_sync(0xffffffffu, c0, srcB);
                float x1b = __shfl_sync(0xffffffffu, c1, srcB);
                float y0b = __shfl_sync(0xffffffffu, c2, srcB);
                float y1b = __shfl_sync(0xffffffffu, c3, srcB);
                const bool odd = (t & 1);
                float pa0 = odd ? x1 : x0;
                float pa1 = odd ? y1 : y0;
                float pa2 = odd ? x1b : x0b;
                float pa3 = odd ? y1b : y0b;
                float2 s0 = splt(pa0), s1 = splt(pa1), s2 = splt(pa2), s3 = splt(pa3);
                unsigned pah[4] = {__float_as_uint(s0.x), __float_as_uint(s1.x),
                                   __float_as_uint(s2.x), __float_as_uint(s3.x)};
                unsigned pal[4] = {__float_as_uint(s0.y), __float_as_uint(s1.y),
                                   __float_as_uint(s2.y), __float_as_uint(s3.y)};
#pragma unroll
                for (int nt = 0; nt < 8; nt++)
                    mma3(ofr[mt][nt], pah, pal, vbh0[nt], vbh1[nt], vbl0[nt], vbl1[nt]);
            }
        }
    }

    // ---- write O ----
    float inv[4];
#pragma unroll
    for (int i = 0; i < 4; i++) inv[i] = 1.f / l_i[i];
#pragma unroll
    for (int mt = 0; mt < 2; mt++) {
#pragma unroll
        for (int nt = 0; nt < 8; nt++) {
            const int d = h * HD + nt * 8 + 2 * t;
#pragma unroll
            for (int half = 0; half < 2; half++) {
                const int r = q0 + wr + mt * 16 + g + half * 8;
                *reinterpret_cast<float2*>(g_wv + (size_t)r * DM + d) =
                    make_float2(ofr[mt][nt][half * 2 + 0] * inv[mt * 2 + half],
                                ofr[mt][nt][half * 2 + 1] * inv[mt * 2 + half]);
            }
        }
    }
}

// ---------------------------------------------------------------------------
extern "C" void kernel_launch(void* const* d_in, const int* in_sizes, int n_in,
                              void* d_out, int out_size)
{
    const float* x    = (const float*)d_in[0];
    const float* mask = (const float*)d_in[1];
    const float* Wq   = (const float*)d_in[2];
    const float* bq   = (const float*)d_in[3];
    const float* Wk   = (const float*)d_in[4];
    const float* Wv   = (const float*)d_in[5];
    const float* bv   = (const float*)d_in[6];
    const float* Wo   = (const float*)d_in[7];
    const float* bo   = (const float*)d_in[8];
    const float* Zf   = (const float*)d_in[9];
    const float* invf = (const float*)d_in[10];

    float* out = (float*)d_out;                       // [2048, 1024]
    float* qk  = out + (size_t)SQ * DM;               // [16, 2048, 2048]

    const int proj_smem = 2 * 2 * PJ_BUF * (int)sizeof(float2);   // 81920
    const int attn_smem = (256 * AQ_STR + 2 * 64 * AQ_STR) * (int)sizeof(float2); // 208896

    static bool attrs_set = false;
    if (!attrs_set) {
        cudaFuncSetAttribute(qkv_gemm, cudaFuncAttributeMaxDynamicSharedMemorySize, proj_smem);
        cudaFuncSetAttribute(out_gemm, cudaFuncAttributeMaxDynamicSharedMemorySize, proj_smem);
        cudaFuncSetAttribute(attn_kernel, cudaFuncAttributeMaxDynamicSharedMemorySize, attn_smem);
        attrs_set = true;
    }

    rope_table<<<256, 256>>>(invf);

    qkv_gemm<<<dim3(DM / 128, SQ / 128, 3), 256, proj_smem>>>(x, Wq, Wk, Wv, bq, bv);

    attn_kernel<<<dim3(SQ / 256, NH), 256, attn_smem>>>(mask, Zf, qk);

    out_gemm<<<dim3(DM / 128, SQ / 128), 256, proj_smem>>>(Wo, bo, out);
}

// round 5
// speedup vs baseline: 3.0277x; 1.9904x over previous
#include <cuda_runtime.h>
#include <cuda_bf16.h>
#include <math.h>

#define SQ 2048
#define DM 1024
#define NH 16
#define HD 64

// Scratch (allocation-free: device globals)
static __device__ float g_q[NH * SQ * HD];
static __device__ float g_k[NH * SQ * HD];
static __device__ float g_v[NH * SQ * HD];
static __device__ float g_wv[SQ * DM];
static __device__ float g_cos[SQ * 32];
static __device__ float g_sin[SQ * 32];

// ---------------- helpers ----------------
__device__ __forceinline__ unsigned sptr(const void* p) {
    return (unsigned)__cvta_generic_to_shared(p);
}
__device__ __forceinline__ void ldsm4(unsigned& r0, unsigned& r1, unsigned& r2,
                                      unsigned& r3, unsigned a) {
    asm volatile("ldmatrix.sync.aligned.m8n8.x4.shared.b16 {%0,%1,%2,%3},[%4];"
                 : "=r"(r0), "=r"(r1), "=r"(r2), "=r"(r3) : "r"(a));
}
__device__ __forceinline__ void ldsm4t(unsigned& r0, unsigned& r1, unsigned& r2,
                                       unsigned& r3, unsigned a) {
    asm volatile("ldmatrix.sync.aligned.m8n8.x4.trans.shared.b16 {%0,%1,%2,%3},[%4];"
                 : "=r"(r0), "=r"(r1), "=r"(r2), "=r"(r3) : "r"(a));
}
__device__ __forceinline__ void mma16(float* c, const unsigned a[4],
                                      unsigned b0, unsigned b1) {
    asm volatile(
        "mma.sync.aligned.m16n8k16.row.col.f32.bf16.bf16.f32 "
        "{%0,%1,%2,%3},{%4,%5,%6,%7},{%8,%9},{%0,%1,%2,%3};"
        : "+f"(c[0]), "+f"(c[1]), "+f"(c[2]), "+f"(c[3])
        : "r"(a[0]), "r"(a[1]), "r"(a[2]), "r"(a[3]), "r"(b0), "r"(b1));
}
__device__ __forceinline__ void splitf(float x, __nv_bfloat16& h, __nv_bfloat16& l) {
    h = __float2bfloat16(x);
    l = __float2bfloat16(x - __bfloat162float(h));
}
__device__ __forceinline__ unsigned pkbf(__nv_bfloat16 a, __nv_bfloat16 b) {
    __nv_bfloat162 t = __halves2bfloat162(a, b);
    return *reinterpret_cast<unsigned*>(&t);
}
__device__ __forceinline__ void split2(float x, float y, unsigned& h, unsigned& l) {
    __nv_bfloat16 hx, lx, hy, ly;
    splitf(x, hx, lx);
    splitf(y, hy, ly);
    h = pkbf(hx, hy);
    l = pkbf(lx, ly);
}

// ---------------------------------------------------------------------------
// RoPE cos/sin table, fp64-accurate. idx = s*32 + j.
// ---------------------------------------------------------------------------
__global__ void rope_table(const float* __restrict__ inv_freq)
{
    const int idx = blockIdx.x * 256 + threadIdx.x;
    const int s = idx >> 5;
    const int j = idx & 31;
    const double f = (double)s * (double)inv_freq[j];
    g_cos[idx] = (float)cos(f);
    g_sin[idx] = (float)sin(f);
}

// ---------------------------------------------------------------------------
// Projection GEMM core (bf16 3-term split): C = A[M,K] * W[N,K]^T
// CTA 128x128, BK=32, 256 threads = 8 warps (2m x 4n), warp tile 64x32.
// smem: hi/lo bf16 matrices, row stride 40 bf16 (80B -> conflict-free ldmatrix).
// ---------------------------------------------------------------------------
#define PK 40
#define PBUF (128 * PK)

__device__ __forceinline__ void proj_core(
    const float* __restrict__ A, const float* __restrict__ W,
    int m0, int n0, __nv_bfloat16* smb, float acc[4][4][4], int tid)
{
    const int lane = tid & 31;
    const int wid = tid >> 5;
    const int wm = (wid & 1) * 64;
    const int wn = (wid >> 1) * 32;
    const int lrow = lane & 15;
    const int lcol = (lane >> 4) * 8;

#pragma unroll
    for (int mt = 0; mt < 4; mt++)
#pragma unroll
        for (int nt = 0; nt < 4; nt++)
#pragma unroll
            for (int r = 0; r < 4; r++) acc[mt][nt][r] = 0.f;

    float4 fa[4], fw[4];
#pragma unroll
    for (int i = 0; i < 4; i++) {
        const int idx = tid + 256 * i;
        const int r = idx >> 3, c = (idx & 7) * 4;
        fa[i] = *reinterpret_cast<const float4*>(A + (size_t)(m0 + r) * DM + c);
        fw[i] = *reinterpret_cast<const float4*>(W + (size_t)(n0 + r) * DM + c);
    }

    int buf = 0;
    for (int kt = 0; kt < DM / 32; kt++) {
        __nv_bfloat16* sAh = smb + buf * 4 * PBUF;
        __nv_bfloat16* sAl = sAh + PBUF;
        __nv_bfloat16* sWh = sAl + PBUF;
        __nv_bfloat16* sWl = sWh + PBUF;

#pragma unroll
        for (int i = 0; i < 4; i++) {
            const int idx = tid + 256 * i;
            const int r = idx >> 3, c = (idx & 7) * 4;
            const float av[4] = {fa[i].x, fa[i].y, fa[i].z, fa[i].w};
            const float wv[4] = {fw[i].x, fw[i].y, fw[i].z, fw[i].w};
#pragma unroll
            for (int j = 0; j < 4; j++) {
                splitf(av[j], sAh[r * PK + c + j], sAl[r * PK + c + j]);
                splitf(wv[j], sWh[r * PK + c + j], sWl[r * PK + c + j]);
            }
        }
        __syncthreads();

        if (kt + 1 < DM / 32) {
            const int k0 = (kt + 1) * 32;
#pragma unroll
            for (int i = 0; i < 4; i++) {
                const int idx = tid + 256 * i;
                const int r = idx >> 3, c = (idx & 7) * 4;
                fa[i] = *reinterpret_cast<const float4*>(A + (size_t)(m0 + r) * DM + k0 + c);
                fw[i] = *reinterpret_cast<const float4*>(W + (size_t)(n0 + r) * DM + k0 + c);
            }
        }

#pragma unroll
        for (int ks = 0; ks < 2; ks++) {
            unsigned ah[4][4], al[4][4];
#pragma unroll
            for (int mt = 0; mt < 4; mt++) {
                const int off = (wm + mt * 16 + lrow) * PK + ks * 16 + lcol;
                ldsm4(ah[mt][0], ah[mt][1], ah[mt][2], ah[mt][3], sptr(sAh + off));
                ldsm4(al[mt][0], al[mt][1], al[mt][2], al[mt][3], sptr(sAl + off));
            }
#pragma unroll
            for (int ng = 0; ng < 2; ng++) {
                unsigned h0, h1, h2, h3, l0, l1, l2, l3;
                const int off = (wn + ng * 16 + lrow) * PK + ks * 16 + lcol;
                ldsm4(h0, h1, h2, h3, sptr(sWh + off));
                ldsm4(l0, l1, l2, l3, sptr(sWl + off));
                // non-trans: b(nt=2ng) = {r0,r2}, b(nt=2ng+1) = {r1,r3}
#pragma unroll
                for (int mt = 0; mt < 4; mt++) {
                    mma16(acc[mt][2 * ng], ah[mt], h0, h2);
                    mma16(acc[mt][2 * ng], ah[mt], l0, l2);
                    mma16(acc[mt][2 * ng], al[mt], h0, h2);
                    mma16(acc[mt][2 * ng + 1], ah[mt], h1, h3);
                    mma16(acc[mt][2 * ng + 1], ah[mt], l1, l3);
                    mma16(acc[mt][2 * ng + 1], al[mt], h1, h3);
                }
            }
        }
        buf ^= 1;
        __syncthreads();
    }
}

// ---------------------------------------------------------------------------
// Fused QKV GEMM + RoPE + scale, head layout output.
// ---------------------------------------------------------------------------
__global__ void __launch_bounds__(256) qkv_gemm(
    const float* __restrict__ x,
    const float* __restrict__ Wq, const float* __restrict__ Wk,
    const float* __restrict__ Wv,
    const float* __restrict__ bq, const float* __restrict__ bv)
{
    extern __shared__ __align__(16) __nv_bfloat16 smb[];
    const int tid = threadIdx.x;
    const int z = blockIdx.z;
    const int m0 = blockIdx.y * 128;
    const int n0 = blockIdx.x * 128;

    const float* W = (z == 0) ? Wq : (z == 1) ? Wk : Wv;
    const float* bias = (z == 0) ? bq : (z == 2) ? bv : nullptr;
    float* out = (z == 0) ? g_q : (z == 1) ? g_k : g_v;

    float acc[4][4][4];
    proj_core(x, W, m0, n0, smb, acc, tid);

    const int lane = tid & 31;
    const int wid = tid >> 5;
    const int g = lane >> 2;
    const int t = lane & 3;
    const int wm = (wid & 1) * 64;
    const int wn = (wid >> 1) * 32;
    const float rsc = 0.35355339059327373f;   // 64^(-1/4)

#pragma unroll
    for (int mt = 0; mt < 4; mt++) {
#pragma unroll
        for (int nt = 0; nt < 4; nt++) {
            const int n = n0 + wn + nt * 8 + 2 * t;
            const int hh = n >> 6;
            const int d = n & 63;
            float b0v = bias ? bias[n] : 0.f;
            float b1v = bias ? bias[n + 1] : 0.f;
#pragma unroll
            for (int half = 0; half < 2; half++) {
                const int m = m0 + wm + mt * 16 + g + half * 8;
                float a = acc[mt][nt][half * 2 + 0] + b0v;
                float b = acc[mt][nt][half * 2 + 1] + b1v;
                float* dst = out + ((size_t)hh * SQ + m) * HD + d;
                if (z < 2) {
                    const int pi = d >> 1;
                    const float c = g_cos[m * 32 + pi];
                    const float s = g_sin[m * 32 + pi];
                    *reinterpret_cast<float2*>(dst) =
                        make_float2(rsc * (a * c - b * s), rsc * (a * s + b * c));
                } else {
                    *reinterpret_cast<float2*>(dst) = make_float2(a, b);
                }
            }
        }
    }
}

// ---------------------------------------------------------------------------
// Output projection: out = g_wv @ Wo^T + bo
// ---------------------------------------------------------------------------
__global__ void __launch_bounds__(256) out_gemm(
    const float* __restrict__ Wo, const float* __restrict__ bo,
    float* __restrict__ C)
{
    extern __shared__ __align__(16) __nv_bfloat16 smb[];
    const int tid = threadIdx.x;
    const int m0 = blockIdx.y * 128;
    const int n0 = blockIdx.x * 128;

    float acc[4][4][4];
    proj_core(g_wv, Wo, m0, n0, smb, acc, tid);

    const int lane = tid & 31;
    const int wid = tid >> 5;
    const int g = lane >> 2;
    const int t = lane & 3;
    const int wm = (wid & 1) * 64;
    const int wn = (wid >> 1) * 32;

#pragma unroll
    for (int mt = 0; mt < 4; mt++) {
#pragma unroll
        for (int nt = 0; nt < 4; nt++) {
            const int n = n0 + wn + nt * 8 + 2 * t;
            const float b0v = bo[n], b1v = bo[n + 1];
#pragma unroll
            for (int half = 0; half < 2; half++) {
                const int m = m0 + wm + mt * 16 + g + half * 8;
                *reinterpret_cast<float2*>(C + (size_t)m * DM + n) =
                    make_float2(acc[mt][nt][half * 2 + 0] + b0v,
                                acc[mt][nt][half * 2 + 1] + b1v);
            }
        }
    }
}

// ---------------------------------------------------------------------------
// Attention (bf16 3-term mma, flash online softmax, qk streamed to gmem).
// CTA: 1 head x 256 q rows. 8 warps x 32 rows each. 64-key tiles.
// smem bf16: sQh/sQl[256][72], sKh/sKl[64][72], sVh/sVl[64][72]  (stride 144B)
// ---------------------------------------------------------------------------
#define AS 72
#define OQH 0
#define OQL 18432
#define OKH 36864
#define OKL 41472
#define OVH 46080
#define OVL 50688

__global__ void __launch_bounds__(256) attn_kernel(
    const float* __restrict__ mask, const float* __restrict__ Zf,
    float* __restrict__ qk_out)
{
    extern __shared__ __align__(16) __nv_bfloat16 smb[];
    __nv_bfloat16* sQh = smb + OQH;
    __nv_bfloat16* sQl = smb + OQL;
    __nv_bfloat16* sKh = smb + OKH;
    __nv_bfloat16* sKl = smb + OKL;
    __nv_bfloat16* sVh = smb + OVH;
    __nv_bfloat16* sVl = smb + OVL;

    const int tid = threadIdx.x;
    const int lane = tid & 31;
    const int wid = tid >> 5;
    const int g = lane >> 2;
    const int t = lane & 3;
    const int lrow = lane & 15;
    const int lcol = (lane >> 4) * 8;
    const int wr = wid * 32;
    const int h = blockIdx.y;
    const int q0 = blockIdx.x * 256;

    const float zfac = fminf(fmaxf(log1pf(expf(Zf[0])), 1e-5f), 1e-4f);

    // ---- load Q block (hi/lo split), coalesced ----
    {
        const float* qg = g_q + ((size_t)h * SQ + q0) * HD;
#pragma unroll
        for (int i = 0; i < 16; i++) {
            const int idx = tid + i * 256;
            const int r = idx >> 4, c = (idx & 15) * 4;
            float4 v = *reinterpret_cast<const float4*>(qg + (size_t)r * HD + c);
            const float av[4] = {v.x, v.y, v.z, v.w};
#pragma unroll
            for (int j = 0; j < 4; j++)
                splitf(av[j], sQh[r * AS + c + j], sQl[r * AS + c + j]);
        }
    }

    float ofr[2][8][4];
    float m_i[4], l_i[4];
#pragma unroll
    for (int mt = 0; mt < 2; mt++)
#pragma unroll
        for (int nt = 0; nt < 8; nt++)
#pragma unroll
            for (int r = 0; r < 4; r++) ofr[mt][nt][r] = 0.f;
#pragma unroll
    for (int i = 0; i < 4; i++) { m_i[i] = -INFINITY; l_i[i] = 0.f; }

    const float2* mask2 = reinterpret_cast<const float2*>(mask);
    float2* qk2 = reinterpret_cast<float2*>(qk_out);

    for (int kt = 0; kt < SQ / 64; kt++) {
        __syncthreads();   // prev tile's K/V reads done (and Q store on iter 0)
        {
            const float* kg = g_k + ((size_t)h * SQ + kt * 64) * HD;
            const float* vg = g_v + ((size_t)h * SQ + kt * 64) * HD;
#pragma unroll
            for (int i = 0; i < 4; i++) {
                const int idx = tid + i * 256;
                const int r = idx >> 4, c = (idx & 15) * 4;
                float4 kv = *reinterpret_cast<const float4*>(kg + (size_t)r * HD + c);
                float4 vv = *reinterpret_cast<const float4*>(vg + (size_t)r * HD + c);
                const float ka[4] = {kv.x, kv.y, kv.z, kv.w};
                const float va[4] = {vv.x, vv.y, vv.z, vv.w};
#pragma unroll
                for (int j = 0; j < 4; j++) {
                    splitf(ka[j], sKh[r * AS + c + j], sKl[r * AS + c + j]);
                    splitf(va[j], sVh[r * AS + c + j], sVl[r * AS + c + j]);
                }
            }
        }
        __syncthreads();

        // ---- S = Q K^T ----
        float sfr[2][8][4];
#pragma unroll
        for (int mt = 0; mt < 2; mt++)
#pragma unroll
            for (int nt = 0; nt < 8; nt++)
#pragma unroll
                for (int r = 0; r < 4; r++) sfr[mt][nt][r] = 0.f;

#pragma unroll
        for (int ks = 0; ks < 4; ks++) {
            unsigned qh[2][4], ql[2][4];
#pragma unroll
            for (int mt = 0; mt < 2; mt++) {
                const int off = (wr + mt * 16 + lrow) * AS + ks * 16 + lcol;
                ldsm4(qh[mt][0], qh[mt][1], qh[mt][2], qh[mt][3], sptr(sQh + off));
                ldsm4(ql[mt][0], ql[mt][1], ql[mt][2], ql[mt][3], sptr(sQl + off));
            }
#pragma unroll
            for (int kg2 = 0; kg2 < 4; kg2++) {
                unsigned h0, h1, h2, h3, l0, l1, l2, l3;
                const int off = (kg2 * 16 + lrow) * AS + ks * 16 + lcol;
                ldsm4(h0, h1, h2, h3, sptr(sKh + off));
                ldsm4(l0, l1, l2, l3, sptr(sKl + off));
                // non-trans: b(nt=2kg2) = {r0,r2}, b(nt=2kg2+1) = {r1,r3}
#pragma unroll
                for (int mt = 0; mt < 2; mt++) {
                    mma16(sfr[mt][2 * kg2], qh[mt], h0, h2);
                    mma16(sfr[mt][2 * kg2], qh[mt], l0, l2);
                    mma16(sfr[mt][2 * kg2], ql[mt], h0, h2);
                    mma16(sfr[mt][2 * kg2 + 1], qh[mt], h1, h3);
                    mma16(sfr[mt][2 * kg2 + 1], qh[mt], l1, l3);
                    mma16(sfr[mt][2 * kg2 + 1], ql[mt], h1, h3);
                }
            }
        }

        // ---- mask + zscale + qk write + row max ----
        float rmax[4];
#pragma unroll
        for (int i = 0; i < 4; i++) rmax[i] = -INFINITY;

#pragma unroll
        for (int nt = 0; nt < 8; nt++) {
            const int c0col = nt * 8 + 2 * t;
            const float k0a = __bfloat162float(sKh[c0col * AS]);
            const float k0b = __bfloat162float(sKl[c0col * AS]);
            const float k1a = __bfloat162float(sKh[(c0col + 1) * AS]);
            const float k1b = __bfloat162float(sKl[(c0col + 1) * AS]);
            const float z0 = (k0a == 0.f && k0b == 0.f) ? zfac : 1.f;
            const float z1 = (k1a == 0.f && k1b == 0.f) ? zfac : 1.f;
#pragma unroll
            for (int mt = 0; mt < 2; mt++) {
#pragma unroll
                for (int half = 0; half < 2; half++) {
                    const int r = q0 + wr + mt * 16 + g + half * 8;
                    float2 mk = mask2[(size_t)r * 1024 + kt * 32 + nt * 4 + t];
                    float s0 = (sfr[mt][nt][half * 2 + 0] + mk.x * z0) * z0;
                    float s1 = (sfr[mt][nt][half * 2 + 1] + mk.y * z1) * z1;
                    qk2[((size_t)h * SQ + r) * 1024 + kt * 32 + nt * 4 + t] =
                        make_float2(s0, s1);
                    sfr[mt][nt][half * 2 + 0] = s0;
                    sfr[mt][nt][half * 2 + 1] = s1;
                    rmax[mt * 2 + half] = fmaxf(rmax[mt * 2 + half], fmaxf(s0, s1));
                }
            }
        }

        // ---- online softmax ----
        float fsc[4];
#pragma unroll
        for (int i = 0; i < 4; i++) {
            float mx = rmax[i];
            mx = fmaxf(mx, __shfl_xor_sync(0xffffffffu, mx, 1));
            mx = fmaxf(mx, __shfl_xor_sync(0xffffffffu, mx, 2));
            const float mn = fmaxf(m_i[i], mx);
            fsc[i] = __expf(m_i[i] - mn);
            m_i[i] = mn;
        }
        float psum[4] = {0.f, 0.f, 0.f, 0.f};
#pragma unroll
        for (int mt = 0; mt < 2; mt++)
#pragma unroll
            for (int nt = 0; nt < 8; nt++)
#pragma unroll
                for (int half = 0; half < 2; half++) {
                    const int i = mt * 2 + half;
                    float p0 = __expf(sfr[mt][nt][half * 2 + 0] - m_i[i]);
                    float p1 = __expf(sfr[mt][nt][half * 2 + 1] - m_i[i]);
                    sfr[mt][nt][half * 2 + 0] = p0;
                    sfr[mt][nt][half * 2 + 1] = p1;
                    psum[i] += p0 + p1;
                }
#pragma unroll
        for (int i = 0; i < 4; i++) {
            float ps = psum[i];
            ps += __shfl_xor_sync(0xffffffffu, ps, 1);
            ps += __shfl_xor_sync(0xffffffffu, ps, 2);
            l_i[i] = l_i[i] * fsc[i] + ps;
        }
#pragma unroll
        for (int mt = 0; mt < 2; mt++)
#pragma unroll
            for (int nt = 0; nt < 8; nt++) {
                ofr[mt][nt][0] *= fsc[mt * 2];
                ofr[mt][nt][1] *= fsc[mt * 2];
                ofr[mt][nt][2] *= fsc[mt * 2 + 1];
                ofr[mt][nt][3] *= fsc[mt * 2 + 1];
            }

        // ---- O += P V : C-fragment of S is directly the A-fragment ----
#pragma unroll
        for (int s = 0; s < 4; s++) {
            unsigned pah[2][4], pal[2][4];
#pragma unroll
            for (int mt = 0; mt < 2; mt++) {
                split2(sfr[mt][2 * s][0], sfr[mt][2 * s][1], pah[mt][0], pal[mt][0]);
                split2(sfr[mt][2 * s][2], sfr[mt][2 * s][3], pah[mt][1], pal[mt][1]);
                split2(sfr[mt][2 * s + 1][0], sfr[mt][2 * s + 1][1], pah[mt][2], pal[mt][2]);
                split2(sfr[mt][2 * s + 1][2], sfr[mt][2 * s + 1][3], pah[mt][3], pal[mt][3]);
            }
#pragma unroll
            for (int dg = 0; dg < 4; dg++) {
                unsigned h0, h1, h2, h3, l0, l1, l2, l3;
                const int off = (s * 16 + lrow) * AS + dg * 16 + lcol;
                ldsm4t(h0, h1, h2, h3, sptr(sVh + off));
                ldsm4t(l0, l1, l2, l3, sptr(sVl + off));
                // trans: b(nt=2dg) = {r0,r1}, b(nt=2dg+1) = {r2,r3}
#pragma unroll
                for (int mt = 0; mt < 2; mt++) {
                    mma16(ofr[mt][2 * dg], pah[mt], h0, h1);
                    mma16(ofr[mt][2 * dg], pah[mt], l0, l1);
                    mma16(ofr[mt][2 * dg], pal[mt], h0, h1);
                    mma16(ofr[mt][2 * dg + 1], pah[mt], h2, h3);
                    mma16(ofr[mt][2 * dg + 1], pah[mt], l2, l3);
                    mma16(ofr[mt][2 * dg + 1], pal[mt], h2, h3);
                }
            }
        }
    }

    // ---- write O ----
    float inv[4];
#pragma unroll
    for (int i = 0; i < 4; i++) inv[i] = 1.f / l_i[i];
#pragma unroll
    for (int mt = 0; mt < 2; mt++) {
#pragma unroll
        for (int nt = 0; nt < 8; nt++) {
            const int d = h * HD + nt * 8 + 2 * t;
#pragma unroll
            for (int half = 0; half < 2; half++) {
                const int r = q0 + wr + mt * 16 + g + half * 8;
                *reinterpret_cast<float2*>(g_wv + (size_t)r * DM + d) =
                    make_float2(ofr[mt][nt][half * 2 + 0] * inv[mt * 2 + half],
                                ofr[mt][nt][half * 2 + 1] * inv[mt * 2 + half]);
            }
        }
    }
}

// ---------------------------------------------------------------------------
extern "C" void kernel_launch(void* const* d_in, const int* in_sizes, int n_in,
                              void* d_out, int out_size)
{
    const float* x    = (const float*)d_in[0];
    const float* mask = (const float*)d_in[1];
    const float* Wq   = (const float*)d_in[2];
    const float* bq   = (const float*)d_in[3];
    const float* Wk   = (const float*)d_in[4];
    const float* Wv   = (const float*)d_in[5];
    const float* bv   = (const float*)d_in[6];
    const float* Wo   = (const float*)d_in[7];
    const float* bo   = (const float*)d_in[8];
    const float* Zf   = (const float*)d_in[9];
    const float* invf = (const float*)d_in[10];

    float* out = (float*)d_out;                       // [2048, 1024]
    float* qk  = out + (size_t)SQ * DM;               // [16, 2048, 2048]

    const int proj_smem = 2 * 4 * PBUF * 2;           // 81920 B
    const int attn_smem = 55296 * 2;                  // 110592 B

    static bool attrs_set = false;
    if (!attrs_set) {
        cudaFuncSetAttribute(qkv_gemm, cudaFuncAttributeMaxDynamicSharedMemorySize, proj_smem);
        cudaFuncSetAttribute(out_gemm, cudaFuncAttributeMaxDynamicSharedMemorySize, proj_smem);
        cudaFuncSetAttribute(attn_kernel, cudaFuncAttributeMaxDynamicSharedMemorySize, attn_smem);
        attrs_set = true;
    }

    rope_table<<<256, 256>>>(invf);

    qkv_gemm<<<dim3(DM / 128, SQ / 128, 3), 256, proj_smem>>>(x, Wq, Wk, Wv, bq, bv);

    attn_kernel<<<dim3(SQ / 256, NH), 256, attn_smem>>>(mask, Zf, qk);

    out_gemm<<<dim3(DM / 128, SQ / 128), 256, proj_smem>>>(Wo, bo, out);
}